// round 2
// baseline (speedup 1.0000x reference)
#include <cuda_runtime.h>
#include <cstdint>

#define N_NODES 100000
#define N_EDGES 625000
#define D 128
#define N_LAYERS 4

// ---------------- scratch (no allocations allowed) ----------------
__device__ __align__(16) float g_h[(size_t)N_NODES * D];  // GEMM output per layer
__device__ __align__(16) float g_x[(size_t)N_NODES * D];  // ping buffer
__device__ __align__(16) float g_deg[N_NODES];
__device__ __align__(16) float g_dinv[N_NODES];
__device__ __align__(16) float g_norm[N_EDGES];

// ---------------- normalization precompute ----------------
__global__ void k_init_deg(float* deg) {
    int i = blockIdx.x * blockDim.x + threadIdx.x;
    if (i < N_NODES) deg[i] = 1.0f;            // self loop
}

__global__ void k_hist(const int* __restrict__ ei, float* deg) {
    int e = blockIdx.x * blockDim.x + threadIdx.x;
    if (e < N_EDGES) {
        int d = ei[N_EDGES + e];               // dst row
        if ((unsigned)d < N_NODES) atomicAdd(&deg[d], 1.0f);
    }
}

__global__ void k_dinv(const float* __restrict__ deg, float* __restrict__ dinv) {
    int i = blockIdx.x * blockDim.x + threadIdx.x;
    if (i < N_NODES) dinv[i] = rsqrtf(deg[i]);
}

__global__ void k_norm(const int* __restrict__ ei,
                       const float* __restrict__ dinv,
                       float* __restrict__ norm) {
    int e = blockIdx.x * blockDim.x + threadIdx.x;
    if (e < N_EDGES) {
        int s = ei[e];
        int d = ei[N_EDGES + e];
        float v = 0.0f;
        if ((unsigned)s < N_NODES && (unsigned)d < N_NODES)
            v = dinv[s] * dinv[d];
        norm[e] = v;
    }
}

// ---------------- GEMM: H = (relu?)X @ W,  X:[N,128] W:[128,128] ----------------
// 256 threads/block, 64 rows per block. W (64KB) + X tile (32KB) in smem.
// Each thread computes 8 rows x 4 cols.
__global__ void __launch_bounds__(256, 2)
k_gemm(const float* __restrict__ X, const float* __restrict__ W,
       float* __restrict__ H, int relu_in) {
    extern __shared__ float smem[];
    float* sW = smem;             // 128*128
    float* sX = smem + D * D;     // 64*128

    int tid = threadIdx.x;
    int row0 = blockIdx.x * 64;

    {
        const float4* W4 = (const float4*)W;
        float4* sW4 = (float4*)sW;
        #pragma unroll
        for (int i = 0; i < 16; i++) sW4[tid + 256 * i] = W4[tid + 256 * i];
    }
    {
        const float4* X4 = (const float4*)(X + (size_t)row0 * D);
        float4* sX4 = (float4*)sX;
        int nrow = N_NODES - row0; if (nrow > 64) nrow = 64;
        int nval4 = nrow * (D / 4);
        #pragma unroll
        for (int i = 0; i < 8; i++) {
            int idx = tid + 256 * i;
            float4 v = make_float4(0.f, 0.f, 0.f, 0.f);
            if (idx < nval4) v = X4[idx];
            if (relu_in) {
                v.x = fmaxf(v.x, 0.f); v.y = fmaxf(v.y, 0.f);
                v.z = fmaxf(v.z, 0.f); v.w = fmaxf(v.w, 0.f);
            }
            sX4[idx] = v;
        }
    }
    __syncthreads();

    int cg = tid & 31;   // cols [4cg, 4cg+4)
    int rg = tid >> 5;   // rows [rg*8, rg*8+8)

    float4 acc[8];
    #pragma unroll
    for (int r = 0; r < 8; r++) acc[r] = make_float4(0.f, 0.f, 0.f, 0.f);

    const float* xbase = sX + (rg * 8) * D;

    #pragma unroll
    for (int k4 = 0; k4 < 32; k4++) {
        float4 xv[8];
        #pragma unroll
        for (int r = 0; r < 8; r++)
            xv[r] = *(const float4*)&xbase[r * D + 4 * k4];
        #pragma unroll
        for (int kk = 0; kk < 4; kk++) {
            float4 w = *(const float4*)&sW[(k4 * 4 + kk) * D + 4 * cg];
            #pragma unroll
            for (int r = 0; r < 8; r++) {
                float xs = (kk == 0) ? xv[r].x : (kk == 1) ? xv[r].y
                         : (kk == 2) ? xv[r].z : xv[r].w;
                acc[r].x += xs * w.x; acc[r].y += xs * w.y;
                acc[r].z += xs * w.z; acc[r].w += xs * w.w;
            }
        }
    }

    #pragma unroll
    for (int r = 0; r < 8; r++) {
        int row = row0 + rg * 8 + r;
        if (row < N_NODES)
            *(float4*)&H[(size_t)row * D + 4 * cg] = acc[r];
    }
}

// ---------------- aggregation ----------------
// out[i] = h[i] * dinv[i]^2 + b   (self-loop contribution + bias)
__global__ void k_agg_init(float* __restrict__ out, const float* __restrict__ h,
                           const float* __restrict__ dinv,
                           const float* __restrict__ b) {
    int idx = blockIdx.x * blockDim.x + threadIdx.x;   // float4 index
    if (idx >= N_NODES * (D / 4)) return;
    int node = idx >> 5;
    int q = idx & 31;
    float s = dinv[node]; s = s * s;
    float4 hv = ((const float4*)h)[idx];
    float4 bv = ((const float4*)b)[q];
    float4 o;
    o.x = hv.x * s + bv.x; o.y = hv.y * s + bv.y;
    o.z = hv.z * s + bv.z; o.w = hv.w * s + bv.w;
    ((float4*)out)[idx] = o;
}

// out[dst] += h[src] * norm[e] : one warp per edge, 16B reduction per lane
__global__ void k_scatter(float* __restrict__ out, const float* __restrict__ h,
                          const float* __restrict__ norm,
                          const int* __restrict__ ei) {
    long long t = (long long)blockIdx.x * blockDim.x + threadIdx.x;
    int e = (int)(t >> 5);
    if (e >= N_EDGES) return;
    int q = (int)(t & 31);
    int s = __ldg(&ei[e]);
    int d = __ldg(&ei[N_EDGES + e]);
    if ((unsigned)s >= N_NODES || (unsigned)d >= N_NODES) return;
    float nv = __ldg(&norm[e]);
    float4 hv = __ldg((const float4*)&h[(size_t)s * D + 4 * q]);
    float4 v;
    v.x = hv.x * nv; v.y = hv.y * nv; v.z = hv.z * nv; v.w = hv.w * nv;
    float* p = &out[(size_t)d * D + 4 * q];
    asm volatile("red.global.add.v4.f32 [%0], {%1, %2, %3, %4};"
                 :: "l"(p), "f"(v.x), "f"(v.y), "f"(v.z), "f"(v.w)
                 : "memory");
}

__global__ void k_relu(float* __restrict__ out) {
    int idx = blockIdx.x * blockDim.x + threadIdx.x;
    if (idx >= N_NODES * (D / 4)) return;
    float4 v = ((float4*)out)[idx];
    v.x = fmaxf(v.x, 0.f); v.y = fmaxf(v.y, 0.f);
    v.z = fmaxf(v.z, 0.f); v.w = fmaxf(v.w, 0.f);
    ((float4*)out)[idx] = v;
}

// ---------------- launch ----------------
extern "C" void kernel_launch(void* const* d_in, const int* in_sizes, int n_in,
                              void* d_out, int out_size) {
    // Identify inputs by element count (robust to metadata ordering):
    //   x: 12,800,000   Ws: 65,536   bs: 512   edge_index: 1,250,000
    const float* x = nullptr;
    const float* Ws = nullptr;
    const float* bs = nullptr;
    const int*   ei = nullptr;
    for (int i = 0; i < n_in; i++) {
        switch (in_sizes[i]) {
            case N_NODES * D:      x  = (const float*)d_in[i]; break;
            case N_LAYERS * D * D: Ws = (const float*)d_in[i]; break;
            case N_LAYERS * D:     bs = (const float*)d_in[i]; break;
            case 2 * N_EDGES:      ei = (const int*)d_in[i];   break;
            default: break;
        }
    }
    float* out = (float*)d_out;

    float *p_h, *p_x, *p_deg, *p_dinv, *p_norm;
    cudaGetSymbolAddress((void**)&p_h,    g_h);
    cudaGetSymbolAddress((void**)&p_x,    g_x);
    cudaGetSymbolAddress((void**)&p_deg,  g_deg);
    cudaGetSymbolAddress((void**)&p_dinv, g_dinv);
    cudaGetSymbolAddress((void**)&p_norm, g_norm);

    const int GEMM_SMEM = (D * D + 64 * D) * (int)sizeof(float);  // 96KB
    cudaFuncSetAttribute(k_gemm, cudaFuncAttributeMaxDynamicSharedMemorySize,
                         GEMM_SMEM);

    const int TPB = 256;
    const int nblk_nodes = (N_NODES + TPB - 1) / TPB;
    const int nblk_edges = (N_EDGES + TPB - 1) / TPB;
    const int nblk_elems = (N_NODES * (D / 4) + TPB - 1) / TPB;
    const int nblk_gemm  = (N_NODES + 63) / 64;
    const long long scatter_threads = (long long)N_EDGES * 32;
    const int nblk_scatter = (int)((scatter_threads + TPB - 1) / TPB);

    // normalization precompute
    k_init_deg<<<nblk_nodes, TPB>>>(p_deg);
    k_hist<<<nblk_edges, TPB>>>(ei, p_deg);
    k_dinv<<<nblk_nodes, TPB>>>(p_deg, p_dinv);
    k_norm<<<nblk_edges, TPB>>>(ei, p_dinv, p_norm);

    // 4 GCN layers
    for (int l = 0; l < N_LAYERS; l++) {
        const float* xin = (l == 0) ? x : p_x;
        int relu_in = (l > 0) ? 1 : 0;
        k_gemm<<<nblk_gemm, TPB, GEMM_SMEM>>>(xin, Ws + (size_t)l * D * D,
                                              p_h, relu_in);
        float* o = (l == N_LAYERS - 1) ? out : p_x;
        k_agg_init<<<nblk_elems, TPB>>>(o, p_h, p_dinv, bs + (size_t)l * D);
        k_scatter<<<nblk_scatter, TPB>>>(o, p_h, p_norm, ei);
    }
    // final relu on d_out
    k_relu<<<nblk_elems, TPB>>>(out);
}

// round 5
// speedup vs baseline: 1.7300x; 1.7300x over previous
#include <cuda_runtime.h>
#include <cuda_bf16.h>
#include <cstdint>

#define N_NODES 100000
#define N_EDGES 625000
#define D 128
#define N_LAYERS 4
#define TILE_M 128
#define NBLK_GEMM ((N_NODES + TILE_M - 1) / TILE_M)   // 782
#define PADK 136                                      // padded k-stride (elements)

// ---------------- device scratch (no allocations allowed) ----------------
__device__ __align__(16) float g_h[(size_t)N_NODES * D];   // GEMM output
__device__ __align__(16) float g_x[(size_t)N_NODES * D];   // layer activations
__device__ __align__(16) float g_dinv[N_NODES];
__device__ int g_cnt[N_NODES];
__device__ int g_rowptr[N_NODES + 1];
__device__ int g_cursor[N_NODES];
__device__ int g_blksum[256];
__device__ int g_srtsrc[N_EDGES];
__device__ __align__(16) float g_srtw[N_EDGES];
// per-layer W transposed [n][k] split into bf16 hi|lo, padded stride PADK
__device__ __align__(16) __nv_bfloat16 g_wsplit[N_LAYERS][2 * D * PADK];

// ---------------- preamble: degree / dinv / CSR sort ----------------
__global__ void k_zero_cnt(int* cnt) {
    int i = blockIdx.x * blockDim.x + threadIdx.x;
    if (i < N_NODES) cnt[i] = 0;
}
__global__ void k_cnt(const int* __restrict__ ei, int* cnt) {
    int e = blockIdx.x * blockDim.x + threadIdx.x;
    if (e < N_EDGES) {
        int d = ei[N_EDGES + e];
        if ((unsigned)d < N_NODES) atomicAdd(&cnt[d], 1);
    }
}
__global__ void k_dinv(const int* __restrict__ cnt, float* __restrict__ dinv) {
    int i = blockIdx.x * blockDim.x + threadIdx.x;
    if (i < N_NODES) dinv[i] = rsqrtf((float)(cnt[i] + 1));   // +1 self loop
}
__global__ void k_scan_block(const int* __restrict__ cnt, int* __restrict__ part,
                             int* __restrict__ blksum) {
    __shared__ int s[512];
    int gid = blockIdx.x * 512 + threadIdx.x;
    int v = (gid < N_NODES) ? cnt[gid] : 0;
    s[threadIdx.x] = v;
    __syncthreads();
    #pragma unroll
    for (int off = 1; off < 512; off <<= 1) {
        int t = (threadIdx.x >= off) ? s[threadIdx.x - off] : 0;
        __syncthreads();
        s[threadIdx.x] += t;
        __syncthreads();
    }
    if (gid < N_NODES) part[gid] = s[threadIdx.x] - v;
    if (threadIdx.x == 511) blksum[blockIdx.x] = s[511];
}
__global__ void k_scan_top(int* blksum, int nblk) {
    __shared__ int s[256];
    int v = (threadIdx.x < nblk) ? blksum[threadIdx.x] : 0;
    s[threadIdx.x] = v;
    __syncthreads();
    #pragma unroll
    for (int off = 1; off < 256; off <<= 1) {
        int t = (threadIdx.x >= off) ? s[threadIdx.x - off] : 0;
        __syncthreads();
        s[threadIdx.x] += t;
        __syncthreads();
    }
    if (threadIdx.x < nblk) blksum[threadIdx.x] = s[threadIdx.x] - v;
}
__global__ void k_scan_add(int* __restrict__ rowptr, const int* __restrict__ blksum,
                           int* __restrict__ cursor) {
    int i = blockIdx.x * blockDim.x + threadIdx.x;
    if (i < N_NODES) {
        int v = rowptr[i] + blksum[i >> 9];
        rowptr[i] = v;
        cursor[i] = v;
    }
    if (i == 0) rowptr[N_NODES] = N_EDGES;
}
__global__ void k_place(const int* __restrict__ ei, const float* __restrict__ dinv,
                        int* cursor, int* __restrict__ srtsrc, float* __restrict__ srtw) {
    int e = blockIdx.x * blockDim.x + threadIdx.x;
    if (e >= N_EDGES) return;
    int s = ei[e];
    int d = ei[N_EDGES + e];
    if ((unsigned)s >= N_NODES || (unsigned)d >= N_NODES) return;
    int pos = atomicAdd(&cursor[d], 1);
    srtsrc[pos] = s;
    srtw[pos] = dinv[s] * dinv[d];
}

// ---------------- W prep: transpose to [n][k], split bf16 hi/lo ----------------
__global__ void k_prep_w(const float* __restrict__ Ws, __nv_bfloat16* __restrict__ wsplit) {
    int l = blockIdx.x;
    const float* W = Ws + (size_t)l * D * D;
    __nv_bfloat16* hi = wsplit + (size_t)l * 2 * D * PADK;
    __nv_bfloat16* lo = hi + D * PADK;
    for (int idx = threadIdx.x; idx < D * D; idx += blockDim.x) {
        int k = idx / D, n = idx % D;          // W[k][n], coalesced over n
        float w = W[idx];
        __nv_bfloat16 h = __float2bfloat16(w);
        float rem = w - __bfloat162float(h);
        hi[n * PADK + k] = h;
        lo[n * PADK + k] = __float2bfloat16(rem);
    }
}

// ---------------- mma.sync bf16 GEMM: H = X @ W (split-bf16, 3 passes) ----------------
__device__ __forceinline__ void mma_bf16(float4& c, uint32_t a0, uint32_t a1,
                                         uint32_t a2, uint32_t a3,
                                         uint32_t b0, uint32_t b1) {
    asm volatile(
        "mma.sync.aligned.m16n8k16.row.col.f32.bf16.bf16.f32 "
        "{%0,%1,%2,%3}, {%4,%5,%6,%7}, {%8,%9}, {%0,%1,%2,%3};"
        : "+f"(c.x), "+f"(c.y), "+f"(c.z), "+f"(c.w)
        : "r"(a0), "r"(a1), "r"(a2), "r"(a3), "r"(b0), "r"(b1));
}

// smem element offsets (bf16 units)
#define SM_AHI 0
#define SM_ALO (D * PADK)          // 17408
#define SM_WHI (2 * D * PADK)      // 34816
#define SM_WLO (3 * D * PADK)      // 52224
#define GEMM_SMEM_BYTES (4 * D * PADK * 2)   // 139264 B

__global__ void __launch_bounds__(256, 1)
k_gemm_mma(const float* __restrict__ X, const __nv_bfloat16* __restrict__ Wsplit,
           float* __restrict__ H) {
    extern __shared__ __nv_bfloat16 sm[];
    __nv_bfloat16* sAhi = sm + SM_AHI;
    __nv_bfloat16* sAlo = sm + SM_ALO;
    __nv_bfloat16* sWhi = sm + SM_WHI;

    int tid = threadIdx.x;
    int wid = tid >> 5;
    int lane = tid & 31;
    int row0 = blockIdx.x * TILE_M;
    int nrows = N_NODES - row0;
    if (nrows > TILE_M) nrows = TILE_M;

    // stage W hi+lo: contiguous 2*D*PADK bf16 = 8704 float4
    {
        const float4* src = (const float4*)Wsplit;
        float4* dst = (float4*)sWhi;
        #pragma unroll
        for (int i = 0; i < 17; i++) {
            int idx = tid + 256 * i;
            if (idx < (2 * D * PADK) / 8) dst[idx] = src[idx];
        }
    }
    // stage A: load X fp32, split into bf16 hi/lo, padded-stride store
    {
        const float4* X4 = (const float4*)(X + (size_t)row0 * D);
        #pragma unroll
        for (int i = 0; i < 16; i++) {
            int idx4 = tid + 256 * i;          // 4096 float4s = 128x128
            int row = idx4 >> 5;
            int col = (idx4 & 31) * 4;
            float4 v = make_float4(0.f, 0.f, 0.f, 0.f);
            if (row < nrows) v = X4[idx4];
            __nv_bfloat162 h0 = __floats2bfloat162_rn(v.x, v.y);
            __nv_bfloat162 h1 = __floats2bfloat162_rn(v.z, v.w);
            float rx = v.x - __bfloat162float(h0.x);
            float ry = v.y - __bfloat162float(h0.y);
            float rz = v.z - __bfloat162float(h1.x);
            float rw = v.w - __bfloat162float(h1.y);
            __nv_bfloat162 l0 = __floats2bfloat162_rn(rx, ry);
            __nv_bfloat162 l1 = __floats2bfloat162_rn(rz, rw);
            uint2 hv, lv;
            hv.x = *(uint32_t*)&h0; hv.y = *(uint32_t*)&h1;
            lv.x = *(uint32_t*)&l0; lv.y = *(uint32_t*)&l1;
            *(uint2*)&sAhi[row * PADK + col] = hv;
            *(uint2*)&sAlo[row * PADK + col] = lv;
        }
    }
    __syncthreads();

    // warp w computes rows [m0, m0+16): fragment rows m0+g and m0+g+8
    int g = lane >> 2;           // group id 0..7
    int tq = lane & 3;           // thread-in-group 0..3
    int m0 = wid * 16;

    float4 acc[16];
    #pragma unroll
    for (int nc = 0; nc < 16; nc++) acc[nc] = make_float4(0.f, 0.f, 0.f, 0.f);

    // pass list: Ahi*Whi + Ahi*Wlo + Alo*Whi
    #pragma unroll
    for (int pass = 0; pass < 3; pass++) {
        const __nv_bfloat16* pA = (pass == 2) ? (sm + SM_ALO) : (sm + SM_AHI);
        const __nv_bfloat16* pW = (pass == 1) ? (sm + SM_WLO) : (sm + SM_WHI);
        const uint32_t* arow0 = (const uint32_t*)(pA + (m0 + g) * PADK);
        const uint32_t* arow8 = (const uint32_t*)(pA + (m0 + g + 8) * PADK);
        #pragma unroll
        for (int kc = 0; kc < 8; kc++) {
            uint32_t a0 = arow0[kc * 8 + tq];
            uint32_t a1 = arow8[kc * 8 + tq];
            uint32_t a2 = arow0[kc * 8 + tq + 4];
            uint32_t a3 = arow8[kc * 8 + tq + 4];
            #pragma unroll
            for (int nc = 0; nc < 16; nc++) {
                const uint32_t* brow = (const uint32_t*)(pW + (nc * 8 + g) * PADK);
                uint32_t b0 = brow[kc * 8 + tq];
                uint32_t b1 = brow[kc * 8 + tq + 4];
                mma_bf16(acc[nc], a0, a1, a2, a3, b0, b1);
            }
        }
    }

    // store: c.x,c.y -> (rowA, t2..t2+1); c.z,c.w -> (rowA+8, ...)
    int rowA = row0 + m0 + g;
    int rowB = rowA + 8;
    int t2 = tq * 2;
    #pragma unroll
    for (int nc = 0; nc < 16; nc++) {
        int col = nc * 8 + t2;
        if (rowA < N_NODES)
            *(float2*)&H[(size_t)rowA * D + col] = make_float2(acc[nc].x, acc[nc].y);
        if (rowB < N_NODES)
            *(float2*)&H[(size_t)rowB * D + col] = make_float2(acc[nc].z, acc[nc].w);
    }
}

// ---------------- CSR aggregation: out = relu(S h + self + bias) ----------------
__global__ void __launch_bounds__(256)
k_agg(float* __restrict__ out, const float* __restrict__ h,
      const float* __restrict__ dinv, const float* __restrict__ b,
      const int* __restrict__ rowptr, const int* __restrict__ srtsrc,
      const float* __restrict__ srtw) {
    int gw = (blockIdx.x * 256 + threadIdx.x) >> 5;
    int lane = threadIdx.x & 31;
    if (gw >= N_NODES) return;
    int v = gw;
    float dv = dinv[v];
    float s2 = dv * dv;
    float4 acc = __ldg((const float4*)&h[(size_t)v * D + 4 * lane]);
    float4 bv = __ldg((const float4*)&b[4 * lane]);
    acc.x = acc.x * s2 + bv.x;
    acc.y = acc.y * s2 + bv.y;
    acc.z = acc.z * s2 + bv.z;
    acc.w = acc.w * s2 + bv.w;
    float4 acc2 = make_float4(0.f, 0.f, 0.f, 0.f);
    int e0 = __ldg(&rowptr[v]);
    int e1 = __ldg(&rowptr[v + 1]);
    int e = e0;
    for (; e + 1 < e1; e += 2) {
        int sa = __ldg(&srtsrc[e]);
        int sb = __ldg(&srtsrc[e + 1]);
        float wa = __ldg(&srtw[e]);
        float wb = __ldg(&srtw[e + 1]);
        float4 ha = __ldg((const float4*)&h[(size_t)sa * D + 4 * lane]);
        float4 hb = __ldg((const float4*)&h[(size_t)sb * D + 4 * lane]);
        acc.x += ha.x * wa; acc.y += ha.y * wa;
        acc.z += ha.z * wa; acc.w += ha.w * wa;
        acc2.x += hb.x * wb; acc2.y += hb.y * wb;
        acc2.z += hb.z * wb; acc2.w += hb.w * wb;
    }
    if (e < e1) {
        int sa = __ldg(&srtsrc[e]);
        float wa = __ldg(&srtw[e]);
        float4 ha = __ldg((const float4*)&h[(size_t)sa * D + 4 * lane]);
        acc.x += ha.x * wa; acc.y += ha.y * wa;
        acc.z += ha.z * wa; acc.w += ha.w * wa;
    }
    acc.x = fmaxf(acc.x + acc2.x, 0.f);
    acc.y = fmaxf(acc.y + acc2.y, 0.f);
    acc.z = fmaxf(acc.z + acc2.z, 0.f);
    acc.w = fmaxf(acc.w + acc2.w, 0.f);
    *(float4*)&out[(size_t)v * D + 4 * lane] = acc;
}

// ---------------- launch ----------------
extern "C" void kernel_launch(void* const* d_in, const int* in_sizes, int n_in,
                              void* d_out, int out_size) {
    const float* x = nullptr;
    const float* Ws = nullptr;
    const float* bs = nullptr;
    const int*   ei = nullptr;
    for (int i = 0; i < n_in; i++) {
        switch (in_sizes[i]) {
            case N_NODES * D:      x  = (const float*)d_in[i]; break;
            case N_LAYERS * D * D: Ws = (const float*)d_in[i]; break;
            case N_LAYERS * D:     bs = (const float*)d_in[i]; break;
            case 2 * N_EDGES:      ei = (const int*)d_in[i];   break;
            default: break;
        }
    }
    float* out = (float*)d_out;

    float *p_h, *p_x, *p_dinv, *p_srtw;
    int *p_cnt, *p_rowptr, *p_cursor, *p_blksum, *p_srtsrc;
    __nv_bfloat16* p_wsplit;
    cudaGetSymbolAddress((void**)&p_h, g_h);
    cudaGetSymbolAddress((void**)&p_x, g_x);
    cudaGetSymbolAddress((void**)&p_dinv, g_dinv);
    cudaGetSymbolAddress((void**)&p_cnt, g_cnt);
    cudaGetSymbolAddress((void**)&p_rowptr, g_rowptr);
    cudaGetSymbolAddress((void**)&p_cursor, g_cursor);
    cudaGetSymbolAddress((void**)&p_blksum, g_blksum);
    cudaGetSymbolAddress((void**)&p_srtsrc, g_srtsrc);
    cudaGetSymbolAddress((void**)&p_srtw, g_srtw);
    cudaGetSymbolAddress((void**)&p_wsplit, g_wsplit);

    cudaFuncSetAttribute(k_gemm_mma, cudaFuncAttributeMaxDynamicSharedMemorySize,
                         GEMM_SMEM_BYTES);

    const int TPB = 256;
    const int nb_nodes = (N_NODES + TPB - 1) / TPB;
    const int nb_edges = (N_EDGES + TPB - 1) / TPB;
    const int nb_scan  = (N_NODES + 511) / 512;          // 196
    const int nb_agg   = (N_NODES * 32 + TPB - 1) / TPB; // 12500

    // preamble: degree, dinv, CSR counting sort, W prep
    k_zero_cnt<<<nb_nodes, TPB>>>(p_cnt);
    k_cnt<<<nb_edges, TPB>>>(ei, p_cnt);
    k_dinv<<<nb_nodes, TPB>>>(p_cnt, p_dinv);
    k_scan_block<<<nb_scan, 512>>>(p_cnt, p_rowptr, p_blksum);
    k_scan_top<<<1, 256>>>(p_blksum, nb_scan);
    k_scan_add<<<nb_nodes, TPB>>>(p_rowptr, p_blksum, p_cursor);
    k_place<<<nb_edges, TPB>>>(ei, p_dinv, p_cursor, p_srtsrc, p_srtw);
    k_prep_w<<<N_LAYERS, TPB>>>(Ws, p_wsplit);

    // 4 GCN layers
    for (int l = 0; l < N_LAYERS; l++) {
        const float* xin = (l == 0) ? x : p_x;
        k_gemm_mma<<<NBLK_GEMM, TPB, GEMM_SMEM_BYTES>>>(
            xin, p_wsplit + (size_t)l * 2 * D * PADK, p_h);
        float* o = (l == N_LAYERS - 1) ? out : p_x;
        k_agg<<<nb_agg, TPB>>>(o, p_h, p_dinv, bs + (size_t)l * D,
                               p_rowptr, p_srtsrc, p_srtw);
    }
}

// round 6
// speedup vs baseline: 1.7610x; 1.0179x over previous
#include <cuda_runtime.h>
#include <cuda_bf16.h>
#include <cstdint>

#define N_NODES 100000
#define N_EDGES 625000
#define D 128
#define N_LAYERS 4
#define TILE_M 128
#define NBLK_GEMM ((N_NODES + TILE_M - 1) / TILE_M)   // 782
#define PADK 136                                      // padded k-stride (elements)

// ---------------- device scratch (no allocations allowed) ----------------
__device__ __align__(16) float g_h[(size_t)N_NODES * D];   // GEMM output
__device__ __align__(16) float g_x[(size_t)N_NODES * D];   // layer activations
__device__ __align__(16) float g_dinv[N_NODES];
__device__ int g_cnt[N_NODES];
__device__ int g_rowptr[N_NODES + 1];
__device__ int g_cursor[N_NODES];
__device__ int g_blksum[256];
__device__ int g_srtsrc[N_EDGES];
__device__ __align__(16) float g_srtw[N_EDGES];
// per-layer W transposed [n][k] split into bf16 hi|lo, padded stride PADK
__device__ __align__(16) __nv_bfloat16 g_wsplit[N_LAYERS][2 * D * PADK];

// ---------------- preamble ----------------
// combined: blocks 0..3 prep W (transpose+split), blocks >=4 zero cnt
__global__ void k_init(const float* __restrict__ Ws,
                       __nv_bfloat16* __restrict__ wsplit, int* __restrict__ cnt) {
    if (blockIdx.x < N_LAYERS) {
        int l = blockIdx.x;
        const float* W = Ws + (size_t)l * D * D;
        __nv_bfloat16* hi = wsplit + (size_t)l * 2 * D * PADK;
        __nv_bfloat16* lo = hi + D * PADK;
        for (int idx = threadIdx.x; idx < D * D; idx += blockDim.x) {
            int k = idx / D, n = idx % D;      // W[k][n]
            float w = W[idx];
            __nv_bfloat16 h = __float2bfloat16(w);
            float rem = w - __bfloat162float(h);
            hi[n * PADK + k] = h;
            lo[n * PADK + k] = __float2bfloat16(rem);
        }
    } else {
        int i = (blockIdx.x - N_LAYERS) * blockDim.x + threadIdx.x;
        if (i < N_NODES) cnt[i] = 0;
    }
}
__global__ void k_cnt(const int* __restrict__ ei, int* cnt) {
    int e = blockIdx.x * blockDim.x + threadIdx.x;
    if (e < N_EDGES) {
        int d = ei[N_EDGES + e];
        if ((unsigned)d < N_NODES) atomicAdd(&cnt[d], 1);
    }
}
// block-local exclusive scan of cnt -> rowptr(partial), raw block total -> blksum,
// and dinv fused in
__global__ void k_scan_block(const int* __restrict__ cnt, int* __restrict__ part,
                             int* __restrict__ blksum, float* __restrict__ dinv) {
    __shared__ int s[512];
    int gid = blockIdx.x * 512 + threadIdx.x;
    int v = (gid < N_NODES) ? cnt[gid] : 0;
    s[threadIdx.x] = v;
    __syncthreads();
    #pragma unroll
    for (int off = 1; off < 512; off <<= 1) {
        int t = (threadIdx.x >= off) ? s[threadIdx.x - off] : 0;
        __syncthreads();
        s[threadIdx.x] += t;
        __syncthreads();
    }
    if (gid < N_NODES) {
        part[gid] = s[threadIdx.x] - v;
        dinv[gid] = rsqrtf((float)(v + 1));   // +1 self loop
    }
    if (threadIdx.x == 511) blksum[blockIdx.x] = s[511];
}
// fused top-level scan + add: each block reduces blksum[0..bid) itself
__global__ void k_scan_add(int* __restrict__ rowptr, const int* __restrict__ blksum,
                           int* __restrict__ cursor) {
    __shared__ int red[512];
    int bid = blockIdx.x, tid = threadIdx.x;
    int a = 0;
    for (int j = tid; j < bid; j += 512) a += blksum[j];
    red[tid] = a;
    __syncthreads();
    #pragma unroll
    for (int off = 256; off > 0; off >>= 1) {
        if (tid < off) red[tid] += red[tid + off];
        __syncthreads();
    }
    int prefix = red[0];
    int i = bid * 512 + tid;
    if (i < N_NODES) {
        int v = rowptr[i] + prefix;
        rowptr[i] = v;
        cursor[i] = v;
    }
    if (i == 0) rowptr[N_NODES] = N_EDGES;
}
__global__ void k_place(const int* __restrict__ ei, const float* __restrict__ dinv,
                        int* cursor, int* __restrict__ srtsrc, float* __restrict__ srtw) {
    int e = blockIdx.x * blockDim.x + threadIdx.x;
    if (e >= N_EDGES) return;
    int s = ei[e];
    int d = ei[N_EDGES + e];
    if ((unsigned)s >= N_NODES || (unsigned)d >= N_NODES) return;
    int pos = atomicAdd(&cursor[d], 1);
    srtsrc[pos] = s;
    srtw[pos] = dinv[s] * dinv[d];
}

// ---------------- mma.sync bf16 GEMM: H = X @ W (split-bf16, 3 passes) ----------------
__device__ __forceinline__ void mma_bf16(float4& c, uint32_t a0, uint32_t a1,
                                         uint32_t a2, uint32_t a3,
                                         uint32_t b0, uint32_t b1) {
    asm volatile(
        "mma.sync.aligned.m16n8k16.row.col.f32.bf16.bf16.f32 "
        "{%0,%1,%2,%3}, {%4,%5,%6,%7}, {%8,%9}, {%0,%1,%2,%3};"
        : "+f"(c.x), "+f"(c.y), "+f"(c.z), "+f"(c.w)
        : "r"(a0), "r"(a1), "r"(a2), "r"(a3), "r"(b0), "r"(b1));
}

// smem element offsets (bf16 units): Ahi | Whi | (Wlo then Alo)
#define SM_AHI 0
#define SM_WHI (D * PADK)
#define SM_WX  (2 * D * PADK)
#define GEMM_SMEM_BYTES (3 * D * PADK * 2)   // 104448 B -> 2 CTAs/SM

// one pass of 128x128x128 over warp tile 32x64
__device__ __forceinline__ void gemm_pass(const __nv_bfloat16* pA, const __nv_bfloat16* pW,
                                          float4 (&acc)[2][8], int wm, int wn,
                                          int g, int tq) {
    const uint32_t* ar[2][2];
    #pragma unroll
    for (int mt = 0; mt < 2; mt++) {
        ar[mt][0] = (const uint32_t*)(pA + (wm * 32 + mt * 16 + g) * PADK);
        ar[mt][1] = (const uint32_t*)(pA + (wm * 32 + mt * 16 + g + 8) * PADK);
    }
    #pragma unroll
    for (int kc = 0; kc < 8; kc++) {
        uint32_t a[2][4];
        #pragma unroll
        for (int mt = 0; mt < 2; mt++) {
            a[mt][0] = ar[mt][0][kc * 8 + tq];
            a[mt][1] = ar[mt][1][kc * 8 + tq];
            a[mt][2] = ar[mt][0][kc * 8 + tq + 4];
            a[mt][3] = ar[mt][1][kc * 8 + tq + 4];
        }
        #pragma unroll
        for (int nc = 0; nc < 8; nc++) {
            const uint32_t* br = (const uint32_t*)(pW + (wn * 64 + nc * 8 + g) * PADK);
            uint32_t b0 = br[kc * 8 + tq];
            uint32_t b1 = br[kc * 8 + tq + 4];
            mma_bf16(acc[0][nc], a[0][0], a[0][1], a[0][2], a[0][3], b0, b1);
            mma_bf16(acc[1][nc], a[1][0], a[1][1], a[1][2], a[1][3], b0, b1);
        }
    }
}

__global__ void __launch_bounds__(256, 2)
k_gemm_mma(const float* __restrict__ X, const __nv_bfloat16* __restrict__ Wsplit,
           float* __restrict__ H) {
    extern __shared__ __nv_bfloat16 sm[];
    int tid = threadIdx.x;
    int wid = tid >> 5;
    int lane = tid & 31;
    int row0 = blockIdx.x * TILE_M;
    int nrows = N_NODES - row0;
    if (nrows > TILE_M) nrows = TILE_M;

    // stage W hi+lo (contiguous 2*D*PADK bf16 = 4352 float4)
    {
        const float4* src = (const float4*)Wsplit;
        float4* dst = (float4*)(sm + SM_WHI);
        #pragma unroll
        for (int i = 0; i < 17; i++) {
            int idx = tid + 256 * i;
            if (idx < (2 * D * PADK) / 8) dst[idx] = src[idx];
        }
    }
    // stage A hi only
    {
        const float4* X4 = (const float4*)(X + (size_t)row0 * D);
        __nv_bfloat16* sAhi = sm + SM_AHI;
        #pragma unroll
        for (int i = 0; i < 16; i++) {
            int idx4 = tid + 256 * i;
            int row = idx4 >> 5;
            int col = (idx4 & 31) * 4;
            float4 v = make_float4(0.f, 0.f, 0.f, 0.f);
            if (row < nrows) v = X4[idx4];
            __nv_bfloat162 h0 = __floats2bfloat162_rn(v.x, v.y);
            __nv_bfloat162 h1 = __floats2bfloat162_rn(v.z, v.w);
            uint2 hv;
            hv.x = *(uint32_t*)&h0; hv.y = *(uint32_t*)&h1;
            *(uint2*)&sAhi[row * PADK + col] = hv;
        }
    }
    __syncthreads();

    int wm = wid & 3;        // row group: rows [wm*32, wm*32+32)
    int wn = wid >> 2;       // col group: cols [wn*64, wn*64+64)
    int g = lane >> 2;
    int tq = lane & 3;

    float4 acc[2][8];
    #pragma unroll
    for (int mt = 0; mt < 2; mt++)
        #pragma unroll
        for (int nc = 0; nc < 8; nc++) acc[mt][nc] = make_float4(0.f, 0.f, 0.f, 0.f);

    gemm_pass(sm + SM_AHI, sm + SM_WHI, acc, wm, wn, g, tq);   // Ahi * Whi
    gemm_pass(sm + SM_AHI, sm + SM_WX,  acc, wm, wn, g, tq);   // Ahi * Wlo
    __syncthreads();
    // restage: Alo overwrites Wlo slot
    {
        const float4* X4 = (const float4*)(X + (size_t)row0 * D);
        __nv_bfloat16* sAlo = sm + SM_WX;
        #pragma unroll
        for (int i = 0; i < 16; i++) {
            int idx4 = tid + 256 * i;
            int row = idx4 >> 5;
            int col = (idx4 & 31) * 4;
            float4 v = make_float4(0.f, 0.f, 0.f, 0.f);
            if (row < nrows) v = X4[idx4];
            __nv_bfloat162 h0 = __floats2bfloat162_rn(v.x, v.y);
            __nv_bfloat162 h1 = __floats2bfloat162_rn(v.z, v.w);
            float rx = v.x - __bfloat162float(h0.x);
            float ry = v.y - __bfloat162float(h0.y);
            float rz = v.z - __bfloat162float(h1.x);
            float rw = v.w - __bfloat162float(h1.y);
            __nv_bfloat162 l0 = __floats2bfloat162_rn(rx, ry);
            __nv_bfloat162 l1 = __floats2bfloat162_rn(rz, rw);
            uint2 lv;
            lv.x = *(uint32_t*)&l0; lv.y = *(uint32_t*)&l1;
            *(uint2*)&sAlo[row * PADK + col] = lv;
        }
    }
    __syncthreads();
    gemm_pass(sm + SM_WX, sm + SM_WHI, acc, wm, wn, g, tq);    // Alo * Whi

    // epilogue: float2 stores
    #pragma unroll
    for (int mt = 0; mt < 2; mt++) {
        int rowA = row0 + wm * 32 + mt * 16 + g;
        int rowB = rowA + 8;
        #pragma unroll
        for (int nc = 0; nc < 8; nc++) {
            int col = wn * 64 + nc * 8 + tq * 2;
            if (rowA < N_NODES)
                *(float2*)&H[(size_t)rowA * D + col] =
                    make_float2(acc[mt][nc].x, acc[mt][nc].y);
            if (rowB < N_NODES)
                *(float2*)&H[(size_t)rowB * D + col] =
                    make_float2(acc[mt][nc].z, acc[mt][nc].w);
        }
    }
}

// ---------------- CSR aggregation: out = relu(S h + self + bias) ----------------
__global__ void __launch_bounds__(256)
k_agg(float* __restrict__ out, const float* __restrict__ h,
      const float* __restrict__ dinv, const float* __restrict__ b,
      const int* __restrict__ rowptr, const int* __restrict__ srtsrc,
      const float* __restrict__ srtw) {
    int gw = (blockIdx.x * 256 + threadIdx.x) >> 5;
    int lane = threadIdx.x & 31;
    if (gw >= N_NODES) return;
    int v = gw;
    float dv = dinv[v];
    float s2 = dv * dv;
    float4 acc = __ldg((const float4*)&h[(size_t)v * D + 4 * lane]);
    float4 bv = __ldg((const float4*)&b[4 * lane]);
    acc.x = acc.x * s2 + bv.x;
    acc.y = acc.y * s2 + bv.y;
    acc.z = acc.z * s2 + bv.z;
    acc.w = acc.w * s2 + bv.w;
    float4 acc2 = make_float4(0.f, 0.f, 0.f, 0.f);
    int e0 = __ldg(&rowptr[v]);
    int e1 = __ldg(&rowptr[v + 1]);
    int e = e0;
    for (; e + 3 < e1; e += 4) {
        int s0 = __ldg(&srtsrc[e]);
        int s1 = __ldg(&srtsrc[e + 1]);
        int s2i = __ldg(&srtsrc[e + 2]);
        int s3 = __ldg(&srtsrc[e + 3]);
        float w0 = __ldg(&srtw[e]);
        float w1 = __ldg(&srtw[e + 1]);
        float w2 = __ldg(&srtw[e + 2]);
        float w3 = __ldg(&srtw[e + 3]);
        float4 h0 = __ldg((const float4*)&h[(size_t)s0 * D + 4 * lane]);
        float4 h1 = __ldg((const float4*)&h[(size_t)s1 * D + 4 * lane]);
        float4 h2 = __ldg((const float4*)&h[(size_t)s2i * D + 4 * lane]);
        float4 h3 = __ldg((const float4*)&h[(size_t)s3 * D + 4 * lane]);
        acc.x += h0.x * w0; acc.y += h0.y * w0; acc.z += h0.z * w0; acc.w += h0.w * w0;
        acc2.x += h1.x * w1; acc2.y += h1.y * w1; acc2.z += h1.z * w1; acc2.w += h1.w * w1;
        acc.x += h2.x * w2; acc.y += h2.y * w2; acc.z += h2.z * w2; acc.w += h2.w * w2;
        acc2.x += h3.x * w3; acc2.y += h3.y * w3; acc2.z += h3.z * w3; acc2.w += h3.w * w3;
    }
    for (; e < e1; e++) {
        int sa = __ldg(&srtsrc[e]);
        float wa = __ldg(&srtw[e]);
        float4 ha = __ldg((const float4*)&h[(size_t)sa * D + 4 * lane]);
        acc.x += ha.x * wa; acc.y += ha.y * wa;
        acc.z += ha.z * wa; acc.w += ha.w * wa;
    }
    acc.x = fmaxf(acc.x + acc2.x, 0.f);
    acc.y = fmaxf(acc.y + acc2.y, 0.f);
    acc.z = fmaxf(acc.z + acc2.z, 0.f);
    acc.w = fmaxf(acc.w + acc2.w, 0.f);
    *(float4*)&out[(size_t)v * D + 4 * lane] = acc;
}

// ---------------- launch ----------------
extern "C" void kernel_launch(void* const* d_in, const int* in_sizes, int n_in,
                              void* d_out, int out_size) {
    const float* x = nullptr;
    const float* Ws = nullptr;
    const float* bs = nullptr;
    const int*   ei = nullptr;
    for (int i = 0; i < n_in; i++) {
        switch (in_sizes[i]) {
            case N_NODES * D:      x  = (const float*)d_in[i]; break;
            case N_LAYERS * D * D: Ws = (const float*)d_in[i]; break;
            case N_LAYERS * D:     bs = (const float*)d_in[i]; break;
            case 2 * N_EDGES:      ei = (const int*)d_in[i];   break;
            default: break;
        }
    }
    float* out = (float*)d_out;

    float *p_h, *p_x, *p_dinv, *p_srtw;
    int *p_cnt, *p_rowptr, *p_cursor, *p_blksum, *p_srtsrc;
    __nv_bfloat16* p_wsplit;
    cudaGetSymbolAddress((void**)&p_h, g_h);
    cudaGetSymbolAddress((void**)&p_x, g_x);
    cudaGetSymbolAddress((void**)&p_dinv, g_dinv);
    cudaGetSymbolAddress((void**)&p_cnt, g_cnt);
    cudaGetSymbolAddress((void**)&p_rowptr, g_rowptr);
    cudaGetSymbolAddress((void**)&p_cursor, g_cursor);
    cudaGetSymbolAddress((void**)&p_blksum, g_blksum);
    cudaGetSymbolAddress((void**)&p_srtsrc, g_srtsrc);
    cudaGetSymbolAddress((void**)&p_srtw, g_srtw);
    cudaGetSymbolAddress((void**)&p_wsplit, g_wsplit);

    cudaFuncSetAttribute(k_gemm_mma, cudaFuncAttributeMaxDynamicSharedMemorySize,
                         GEMM_SMEM_BYTES);

    const int TPB = 256;
    const int nb_edges = (N_EDGES + TPB - 1) / TPB;
    const int nb_scan  = (N_NODES + 511) / 512;          // 196
    const int nb_agg   = (N_NODES * 32 + TPB - 1) / TPB; // 12500
    const int nb_init  = N_LAYERS + (N_NODES + TPB - 1) / TPB;  // 395

    // preamble (exactly 5 launches -> ncu -s5 captures first GEMM)
    k_init<<<nb_init, TPB>>>(Ws, p_wsplit, p_cnt);
    k_cnt<<<nb_edges, TPB>>>(ei, p_cnt);
    k_scan_block<<<nb_scan, 512>>>(p_cnt, p_rowptr, p_blksum, p_dinv);
    k_scan_add<<<nb_scan, 512>>>(p_rowptr, p_blksum, p_cursor);
    k_place<<<nb_edges, TPB>>>(ei, p_dinv, p_cursor, p_srtsrc, p_srtw);

    // 4 GCN layers
    for (int l = 0; l < N_LAYERS; l++) {
        const float* xin = (l == 0) ? x : p_x;
        k_gemm_mma<<<NBLK_GEMM, TPB, GEMM_SMEM_BYTES>>>(
            xin, p_wsplit + (size_t)l * 2 * D * PADK, p_h);
        float* o = (l == N_LAYERS - 1) ? out : p_x;
        k_agg<<<nb_agg, TPB>>>(o, p_h, p_dinv, bs + (size_t)l * D,
                               p_rowptr, p_srtsrc, p_srtw);
    }
}